// round 3
// baseline (speedup 1.0000x reference)
#include <cuda_runtime.h>
#include <math.h>

#define S_ 32
#define H_ 768
#define I_ 768
#define E_ 32
#define TOPK_ 4
#define LIMIT_ 7.0f
#define ALPHA_ 1.702f
#define EPS_ 1e-5f

#define TB 8           // max tokens per work chunk
#define MAXW 64        // max work chunks (true worst case is 44)

// Scratch (device globals: allocation-free)
__device__ float g_t[S_ * H_];           // rmsnormed tokens
__device__ int   g_idx[S_ * TOPK_];      // top-k expert ids
__device__ float g_wts[S_ * TOPK_];      // softmax weights
__device__ int   g_cnt[E_];              // tokens per expert
__device__ int   g_sel[E_ * S_];         // sel = s*4+k per expert slot
__device__ float g_act[S_ * TOPK_ * I_]; // post-SwiGLU activations
__device__ int   g_work[MAXW * 3];       // (expert, base, len)
__device__ int   g_nw;

// ---------------------------------------------------------------------------
// Kernel 1: RMSNorm + router (logits, top-4, softmax) + residual init
// ---------------------------------------------------------------------------
__global__ void __launch_bounds__(256) k_norm_router(
    const float* __restrict__ x, const float* __restrict__ nscale,
    const float* __restrict__ gw, const float* __restrict__ gb,
    float* __restrict__ out)
{
    int s   = blockIdx.x;
    int tid = threadIdx.x;
    int lane = tid & 31, wid = tid >> 5;

    __shared__ float sh_t[H_];
    __shared__ float red[8];
    __shared__ float logits[E_];

    float v0[3];
    float ss = 0.f;
#pragma unroll
    for (int q = 0; q < 3; q++) {
        float v = x[s * H_ + tid + 256 * q];
        v0[q] = v;
        ss += v * v;
    }
#pragma unroll
    for (int o = 16; o; o >>= 1) ss += __shfl_xor_sync(0xffffffffu, ss, o);
    if (lane == 0) red[wid] = ss;
    __syncthreads();
    if (tid < 8) {
        float r = red[tid];
#pragma unroll
        for (int o = 4; o; o >>= 1) r += __shfl_xor_sync(0xffu, r, o);
        if (tid == 0) red[0] = r;
    }
    __syncthreads();
    float rms = rsqrtf(red[0] / (float)H_ + EPS_);

#pragma unroll
    for (int q = 0; q < 3; q++) {
        int j = tid + 256 * q;
        float t = v0[q] * rms * nscale[j];
        sh_t[j] = t;
        g_t[s * H_ + j] = t;
        out[s * H_ + j] = v0[q];   // residual init out = x
    }
    __syncthreads();

#pragma unroll
    for (int e4 = 0; e4 < 4; e4++) {
        int e = wid * 4 + e4;
        float acc = 0.f;
        for (int j = lane; j < H_; j += 32) acc += sh_t[j] * gw[e * H_ + j];
#pragma unroll
        for (int o = 16; o; o >>= 1) acc += __shfl_xor_sync(0xffffffffu, acc, o);
        if (lane == 0) logits[e] = acc + gb[e];
    }
    __syncthreads();

    if (tid == 0) {
        float l[E_];
#pragma unroll
        for (int e = 0; e < E_; e++) l[e] = logits[e];
        float vals[TOPK_];
        int   ids[TOPK_];
#pragma unroll
        for (int k = 0; k < TOPK_; k++) {
            float m = -1e30f; int mi = 0;
            for (int e = 0; e < E_; e++) {
                if (l[e] > m) { m = l[e]; mi = e; }
            }
            vals[k] = m; ids[k] = mi; l[mi] = -1e30f;
        }
        float mx = vals[0], sum = 0.f, w[TOPK_];
#pragma unroll
        for (int k = 0; k < TOPK_; k++) { w[k] = __expf(vals[k] - mx); sum += w[k]; }
        float inv = 1.f / sum;
#pragma unroll
        for (int k = 0; k < TOPK_; k++) {
            g_idx[s * TOPK_ + k] = ids[k];
            g_wts[s * TOPK_ + k] = w[k] * inv;
        }
    }
}

// ---------------------------------------------------------------------------
// Kernel 2: build per-expert selection lists + work chunks (single thread)
// ---------------------------------------------------------------------------
__global__ void k_build()
{
    if (threadIdx.x == 0 && blockIdx.x == 0) {
        for (int e = 0; e < E_; e++) g_cnt[e] = 0;
        for (int sel = 0; sel < S_ * TOPK_; sel++) {
            int e = g_idx[sel];
            g_sel[e * S_ + g_cnt[e]] = sel;
            g_cnt[e]++;
        }
        int w = 0;
        for (int e = 0; e < E_; e++) {
            int n = g_cnt[e];
            for (int base = 0; base < n; base += TB) {
                int len = n - base; if (len > TB) len = TB;
                g_work[w * 3 + 0] = e;
                g_work[w * 3 + 1] = base;
                g_work[w * 3 + 2] = len;
                w++;
            }
        }
        g_nw = w;
    }
}

// ---------------------------------------------------------------------------
// Kernel 3: expert MLP-1, row-streaming with register double-buffer,
//           SwiGLU combine in smem epilogue.
// grid (2I_/T1R, MAXW), 256 threads
// ---------------------------------------------------------------------------
#define T1R 64
#define NJ1 (T1R / 8)
__global__ void __launch_bounds__(256) k_mlp1(
    const float* __restrict__ w1, const float* __restrict__ b1)
{
    int widx = blockIdx.y;
    if (widx >= g_nw) return;
    int e    = g_work[widx * 3 + 0];
    int base = g_work[widx * 3 + 1];
    int n    = g_work[widx * 3 + 2];

    __shared__ float sm[TB * H_];       // 24 KB token tile
    __shared__ float sh_h[TB][T1R];     // raw pre-activations
    __shared__ int ssel[TB];

    int tid = threadIdx.x, wid = tid >> 5, lane = tid & 31;

    if (tid < n) ssel[tid] = g_sel[e * S_ + base + tid];
    __syncthreads();
    for (int i = 0; i < n; i++) {
        int s = ssel[i] >> 2;
        for (int j = tid; j < H_; j += 256) sm[i * H_ + j] = g_t[s * H_ + j];
    }
    __syncthreads();

    int rbase = blockIdx.x * T1R;
    const float4* rowp = (const float4*)(w1 + ((size_t)e * 2 * I_ + rbase + wid) * H_);

    float4 wv[6];
#pragma unroll
    for (int q = 0; q < 6; q++) wv[q] = rowp[lane + 32 * q];

#pragma unroll
    for (int jj = 0; jj < NJ1; jj++) {
        float4 wn[6];
        if (jj + 1 < NJ1) {
            const float4* rn = rowp + (size_t)(8 * (jj + 1)) * (H_ / 4);
#pragma unroll
            for (int q = 0; q < 6; q++) wn[q] = rn[lane + 32 * q];
        }
        int r = wid + 8 * jj;
        float bias = b1[e * 2 * I_ + rbase + r];
        for (int i = 0; i < n; i++) {
            const float4* tt = (const float4*)(sm + i * H_);
            float a0 = 0.f, a1 = 0.f;
#pragma unroll
            for (int q = 0; q < 6; q += 2) {
                float4 t0 = tt[lane + 32 * q];
                float4 t1 = tt[lane + 32 * (q + 1)];
                a0 += wv[q].x * t0.x + wv[q].y * t0.y + wv[q].z * t0.z + wv[q].w * t0.w;
                a1 += wv[q+1].x * t1.x + wv[q+1].y * t1.y + wv[q+1].z * t1.z + wv[q+1].w * t1.w;
            }
            float a = a0 + a1;
#pragma unroll
            for (int o = 16; o; o >>= 1) a += __shfl_xor_sync(0xffffffffu, a, o);
            if (lane == 0) sh_h[i][r] = a + bias;
        }
#pragma unroll
        for (int q = 0; q < 6; q++) wv[q] = wn[q];
    }
    __syncthreads();

    // epilogue: combine (gate, linear) pairs -> act
    int items = n * (T1R / 2);
    for (int it = tid; it < items; it += 256) {
        int i = it / (T1R / 2);
        int m = it % (T1R / 2);
        float hg = sh_h[i][2 * m];
        float hl = sh_h[i][2 * m + 1];
        hg = fminf(hg, LIMIT_);
        hl = fminf(fmaxf(hl, -LIMIT_), LIMIT_);
        float sig = 1.f / (1.f + __expf(-ALPHA_ * hg));
        int c = (rbase >> 1) + m;
        g_act[ssel[i] * I_ + c] = hg * sig * (hl + 1.f);
    }
}

// ---------------------------------------------------------------------------
// Kernel 4: expert MLP-2 + weighted accumulation, register double-buffer
// grid (H_/T2C, MAXW), 256 threads
// ---------------------------------------------------------------------------
#define T2C 32
#define NJ2 (T2C / 8)
__global__ void __launch_bounds__(256) k_mlp2(
    const float* __restrict__ w2, const float* __restrict__ b2,
    float* __restrict__ out)
{
    int widx = blockIdx.y;
    if (widx >= g_nw) return;
    int e    = g_work[widx * 3 + 0];
    int base = g_work[widx * 3 + 1];
    int n    = g_work[widx * 3 + 2];

    __shared__ float sm[TB * I_];     // 24 KB act tile
    __shared__ int   ssel[TB];
    __shared__ float swt[TB];

    int tid = threadIdx.x, wid = tid >> 5, lane = tid & 31;

    if (tid < n) {
        int sel = g_sel[e * S_ + base + tid];
        ssel[tid] = sel;
        swt[tid]  = g_wts[sel];
    }
    __syncthreads();
    for (int i = 0; i < n; i++) {
        int sel = ssel[i];
        for (int j = tid; j < I_; j += 256) sm[i * I_ + j] = g_act[sel * I_ + j];
    }
    __syncthreads();

    int cbase = blockIdx.x * T2C;
    const float4* rowp = (const float4*)(w2 + ((size_t)e * H_ + cbase + wid) * I_);

    float4 wv[6];
#pragma unroll
    for (int q = 0; q < 6; q++) wv[q] = rowp[lane + 32 * q];

#pragma unroll
    for (int jj = 0; jj < NJ2; jj++) {
        float4 wn[6];
        if (jj + 1 < NJ2) {
            const float4* rn = rowp + (size_t)(8 * (jj + 1)) * (I_ / 4);
#pragma unroll
            for (int q = 0; q < 6; q++) wn[q] = rn[lane + 32 * q];
        }
        int c = cbase + wid + 8 * jj;
        float bias = b2[e * H_ + c];
        for (int i = 0; i < n; i++) {
            const float4* av = (const float4*)(sm + i * I_);
            float a0 = 0.f, a1 = 0.f;
#pragma unroll
            for (int q = 0; q < 6; q += 2) {
                float4 x0 = av[lane + 32 * q];
                float4 x1 = av[lane + 32 * (q + 1)];
                a0 += wv[q].x * x0.x + wv[q].y * x0.y + wv[q].z * x0.z + wv[q].w * x0.w;
                a1 += wv[q+1].x * x1.x + wv[q+1].y * x1.y + wv[q+1].z * x1.z + wv[q+1].w * x1.w;
            }
            float acc = a0 + a1;
#pragma unroll
            for (int o = 16; o; o >>= 1) acc += __shfl_xor_sync(0xffffffffu, acc, o);
            if (lane == 0) {
                int s = ssel[i] >> 2;
                atomicAdd(&out[s * H_ + c], swt[i] * (acc + bias));
            }
        }
#pragma unroll
        for (int q = 0; q < 6; q++) wv[q] = wn[q];
    }
}

// ---------------------------------------------------------------------------
extern "C" void kernel_launch(void* const* d_in, const int* in_sizes, int n_in,
                              void* d_out, int out_size)
{
    const float* x  = (const float*)d_in[0];
    const float* ns = (const float*)d_in[1];
    const float* gw = (const float*)d_in[2];
    const float* gb = (const float*)d_in[3];
    const float* w1 = (const float*)d_in[4];
    const float* b1 = (const float*)d_in[5];
    const float* w2 = (const float*)d_in[6];
    const float* b2 = (const float*)d_in[7];
    float* out = (float*)d_out;

    k_norm_router<<<S_, 256>>>(x, ns, gw, gb, out);
    k_build<<<1, 32>>>();
    dim3 g1(2 * I_ / T1R, MAXW);   // (24, 64)
    k_mlp1<<<g1, 256>>>(w1, b1);
    dim3 g2(H_ / T2C, MAXW);       // (24, 64)
    k_mlp2<<<g2, 256>>>(w2, b2, out);
}

// round 4
// speedup vs baseline: 1.0899x; 1.0899x over previous
#include <cuda_runtime.h>
#include <math.h>

#define S_ 32
#define H_ 768
#define I_ 768
#define E_ 32
#define TOPK_ 4
#define LIMIT_ 7.0f
#define ALPHA_ 1.702f
#define EPS_ 1e-5f

#define TB 8           // max tokens per work chunk
#define MAXW 64        // max work chunks

// Scratch (device globals: allocation-free)
__device__ float g_t[S_ * H_];           // rmsnormed tokens
__device__ int   g_idx[S_ * TOPK_];      // top-k expert ids
__device__ float g_wts[S_ * TOPK_];      // softmax weights
__device__ int   g_cnt[E_];              // tokens per expert
__device__ int   g_sel[E_ * S_];         // sel = s*4+k per expert slot
__device__ float g_act[S_ * TOPK_ * I_]; // post-SwiGLU activations
__device__ int   g_work[MAXW * 3];       // (expert, base, len)
__device__ int   g_nw;

// Packed reduction: 4 per-thread partials -> lane L holds full sum of a[L&3].
// 6 SHFL total instead of 20.
__device__ __forceinline__ float reduce4(float a0, float a1, float a2, float a3, int lane)
{
    float w0 = (lane & 1) ? a1 : a0;
    float o0 = (lane & 1) ? a0 : a1;
    float b0 = w0 + __shfl_xor_sync(0xffffffffu, o0, 1);
    float w1 = (lane & 1) ? a3 : a2;
    float o1 = (lane & 1) ? a2 : a3;
    float b1 = w1 + __shfl_xor_sync(0xffffffffu, o1, 1);
    float w2 = (lane & 2) ? b1 : b0;
    float o2 = (lane & 2) ? b0 : b1;
    float c  = w2 + __shfl_xor_sync(0xffffffffu, o2, 2);
    c += __shfl_xor_sync(0xffffffffu, c, 4);
    c += __shfl_xor_sync(0xffffffffu, c, 8);
    c += __shfl_xor_sync(0xffffffffu, c, 16);
    return c;
}

// ---------------------------------------------------------------------------
// Kernel 1: RMSNorm + router (logits, top-4, softmax) + residual init
// ---------------------------------------------------------------------------
__global__ void __launch_bounds__(256) k_norm_router(
    const float* __restrict__ x, const float* __restrict__ nscale,
    const float* __restrict__ gw, const float* __restrict__ gb,
    float* __restrict__ out)
{
    int s   = blockIdx.x;
    int tid = threadIdx.x;
    int lane = tid & 31, wid = tid >> 5;

    __shared__ float sh_t[H_];
    __shared__ float red[8];
    __shared__ float logits[E_];

    float v0[3];
    float ss = 0.f;
#pragma unroll
    for (int q = 0; q < 3; q++) {
        float v = x[s * H_ + tid + 256 * q];
        v0[q] = v;
        ss += v * v;
    }
#pragma unroll
    for (int o = 16; o; o >>= 1) ss += __shfl_xor_sync(0xffffffffu, ss, o);
    if (lane == 0) red[wid] = ss;
    __syncthreads();
    if (tid < 8) {
        float r = red[tid];
#pragma unroll
        for (int o = 4; o; o >>= 1) r += __shfl_xor_sync(0xffu, r, o);
        if (tid == 0) red[0] = r;
    }
    __syncthreads();
    float rms = rsqrtf(red[0] / (float)H_ + EPS_);

#pragma unroll
    for (int q = 0; q < 3; q++) {
        int j = tid + 256 * q;
        float t = v0[q] * rms * nscale[j];
        sh_t[j] = t;
        g_t[s * H_ + j] = t;
        out[s * H_ + j] = v0[q];   // residual init out = x
    }
    __syncthreads();

#pragma unroll
    for (int e4 = 0; e4 < 4; e4++) {
        int e = wid * 4 + e4;
        float acc = 0.f;
        for (int j = lane; j < H_; j += 32) acc += sh_t[j] * gw[e * H_ + j];
#pragma unroll
        for (int o = 16; o; o >>= 1) acc += __shfl_xor_sync(0xffffffffu, acc, o);
        if (lane == 0) logits[e] = acc + gb[e];
    }
    __syncthreads();

    if (tid == 0) {
        float l[E_];
#pragma unroll
        for (int e = 0; e < E_; e++) l[e] = logits[e];
        float vals[TOPK_];
        int   ids[TOPK_];
#pragma unroll
        for (int k = 0; k < TOPK_; k++) {
            float m = -1e30f; int mi = 0;
            for (int e = 0; e < E_; e++) {
                if (l[e] > m) { m = l[e]; mi = e; }
            }
            vals[k] = m; ids[k] = mi; l[mi] = -1e30f;
        }
        float mx = vals[0], sum = 0.f, w[TOPK_];
#pragma unroll
        for (int k = 0; k < TOPK_; k++) { w[k] = __expf(vals[k] - mx); sum += w[k]; }
        float inv = 1.f / sum;
#pragma unroll
        for (int k = 0; k < TOPK_; k++) {
            g_idx[s * TOPK_ + k] = ids[k];
            g_wts[s * TOPK_ + k] = w[k] * inv;
        }
    }
}

// ---------------------------------------------------------------------------
// Kernel 2: build per-expert selection lists + work chunks (single thread)
// ---------------------------------------------------------------------------
__global__ void k_build()
{
    if (threadIdx.x == 0 && blockIdx.x == 0) {
        for (int e = 0; e < E_; e++) g_cnt[e] = 0;
        for (int sel = 0; sel < S_ * TOPK_; sel++) {
            int e = g_idx[sel];
            g_sel[e * S_ + g_cnt[e]] = sel;
            g_cnt[e]++;
        }
        int w = 0;
        for (int e = 0; e < E_; e++) {
            int n = g_cnt[e];
            for (int base = 0; base < n; base += TB) {
                int len = n - base; if (len > TB) len = TB;
                g_work[w * 3 + 0] = e;
                g_work[w * 3 + 1] = base;
                g_work[w * 3 + 2] = len;
                w++;
            }
        }
        g_nw = w;
    }
}

// ---------------------------------------------------------------------------
// Kernel 3: expert MLP-1 (raw rows) + SwiGLU epilogue
// grid (2I_/T1R, MAXW), 256 threads; each warp: 4 w1 rows
// ---------------------------------------------------------------------------
#define T1R 32
__global__ void __launch_bounds__(256) k_mlp1(
    const float* __restrict__ w1, const float* __restrict__ b1)
{
    int widx = blockIdx.y;
    if (widx >= g_nw) return;
    int e    = g_work[widx * 3 + 0];
    int base = g_work[widx * 3 + 1];
    int n    = g_work[widx * 3 + 2];

    __shared__ float sm[TB * H_];       // 24 KB token tile
    __shared__ float sh_h[TB][T1R];     // raw pre-activations
    __shared__ int ssel[TB];

    int tid = threadIdx.x, wid = tid >> 5, lane = tid & 31;

    if (tid < n) ssel[tid] = g_sel[e * S_ + base + tid];
    __syncthreads();
    for (int i = 0; i < n; i++) {
        int s = ssel[i] >> 2;
        for (int j = tid; j < H_; j += 256) sm[i * H_ + j] = g_t[s * H_ + j];
    }
    __syncthreads();

    int rbase = blockIdx.x * T1R;
#pragma unroll
    for (int jj = 0; jj < T1R / 8; jj++) {
        int rloc = wid + 8 * jj;
        int r = rbase + rloc;
        const float4* rowp = (const float4*)(w1 + ((size_t)e * 2 * I_ + r) * H_);
        float4 wv[6];
#pragma unroll
        for (int q = 0; q < 6; q++) wv[q] = rowp[lane + 32 * q];
        float bias = b1[e * 2 * I_ + r];

        for (int g4 = 0; g4 < n; g4 += 4) {
            float a[4] = {0.f, 0.f, 0.f, 0.f};
#pragma unroll
            for (int i4 = 0; i4 < 4; i4++) {
                int i = g4 + i4;
                if (i < n) {
                    const float4* tt = (const float4*)(sm + i * H_);
                    float s0 = 0.f, s1 = 0.f;
#pragma unroll
                    for (int q = 0; q < 6; q += 2) {
                        float4 t0 = tt[lane + 32 * q];
                        float4 t1 = tt[lane + 32 * (q + 1)];
                        s0 += wv[q].x * t0.x + wv[q].y * t0.y + wv[q].z * t0.z + wv[q].w * t0.w;
                        s1 += wv[q+1].x * t1.x + wv[q+1].y * t1.y + wv[q+1].z * t1.z + wv[q+1].w * t1.w;
                    }
                    a[i4] = s0 + s1;
                }
            }
            float d = reduce4(a[0], a[1], a[2], a[3], lane);
            if (lane < 4 && g4 + lane < n)
                sh_h[g4 + lane][rloc] = d + bias;
        }
    }
    __syncthreads();

    // epilogue: combine (gate, linear) pairs -> act
    int items = n * (T1R / 2);
    for (int it = tid; it < items; it += 256) {
        int i = it / (T1R / 2);
        int m = it % (T1R / 2);
        float hg = sh_h[i][2 * m];
        float hl = sh_h[i][2 * m + 1];
        hg = fminf(hg, LIMIT_);
        hl = fminf(fmaxf(hl, -LIMIT_), LIMIT_);
        float sig = 1.f / (1.f + __expf(-ALPHA_ * hg));
        int c = (rbase >> 1) + m;
        g_act[ssel[i] * I_ + c] = hg * sig * (hl + 1.f);
    }
}

// ---------------------------------------------------------------------------
// Kernel 4: expert MLP-2 + weighted accumulation into out
// grid (H_/T2C, MAXW), 256 threads; each warp: 4 w2 rows
// ---------------------------------------------------------------------------
#define T2C 32
__global__ void __launch_bounds__(256) k_mlp2(
    const float* __restrict__ w2, const float* __restrict__ b2,
    float* __restrict__ out)
{
    int widx = blockIdx.y;
    if (widx >= g_nw) return;
    int e    = g_work[widx * 3 + 0];
    int base = g_work[widx * 3 + 1];
    int n    = g_work[widx * 3 + 2];

    __shared__ float sm[TB * I_];     // 24 KB act tile
    __shared__ int   ssel[TB];
    __shared__ float swt[TB];

    int tid = threadIdx.x, wid = tid >> 5, lane = tid & 31;

    if (tid < n) {
        int sel = g_sel[e * S_ + base + tid];
        ssel[tid] = sel;
        swt[tid]  = g_wts[sel];
    }
    __syncthreads();
    for (int i = 0; i < n; i++) {
        int sel = ssel[i];
        for (int j = tid; j < I_; j += 256) sm[i * I_ + j] = g_act[sel * I_ + j];
    }
    __syncthreads();

    int cbase = blockIdx.x * T2C;
#pragma unroll
    for (int jj = 0; jj < T2C / 8; jj++) {
        int c = cbase + wid + 8 * jj;
        const float4* rowp = (const float4*)(w2 + ((size_t)e * H_ + c) * I_);
        float4 wv[6];
#pragma unroll
        for (int q = 0; q < 6; q++) wv[q] = rowp[lane + 32 * q];
        float bias = b2[e * H_ + c];

        for (int g4 = 0; g4 < n; g4 += 4) {
            float a[4] = {0.f, 0.f, 0.f, 0.f};
#pragma unroll
            for (int i4 = 0; i4 < 4; i4++) {
                int i = g4 + i4;
                if (i < n) {
                    const float4* av = (const float4*)(sm + i * I_);
                    float s0 = 0.f, s1 = 0.f;
#pragma unroll
                    for (int q = 0; q < 6; q += 2) {
                        float4 x0 = av[lane + 32 * q];
                        float4 x1 = av[lane + 32 * (q + 1)];
                        s0 += wv[q].x * x0.x + wv[q].y * x0.y + wv[q].z * x0.z + wv[q].w * x0.w;
                        s1 += wv[q+1].x * x1.x + wv[q+1].y * x1.y + wv[q+1].z * x1.z + wv[q+1].w * x1.w;
                    }
                    a[i4] = s0 + s1;
                }
            }
            float d = reduce4(a[0], a[1], a[2], a[3], lane);
            int i = g4 + lane;
            if (lane < 4 && i < n) {
                int s = ssel[i] >> 2;
                atomicAdd(&out[s * H_ + c], swt[i] * (d + bias));
            }
        }
    }
}

// ---------------------------------------------------------------------------
extern "C" void kernel_launch(void* const* d_in, const int* in_sizes, int n_in,
                              void* d_out, int out_size)
{
    const float* x  = (const float*)d_in[0];
    const float* ns = (const float*)d_in[1];
    const float* gw = (const float*)d_in[2];
    const float* gb = (const float*)d_in[3];
    const float* w1 = (const float*)d_in[4];
    const float* b1 = (const float*)d_in[5];
    const float* w2 = (const float*)d_in[6];
    const float* b2 = (const float*)d_in[7];
    float* out = (float*)d_out;

    k_norm_router<<<S_, 256>>>(x, ns, gw, gb, out);
    k_build<<<1, 32>>>();
    dim3 g1(2 * I_ / T1R, MAXW);   // (48, 64)
    k_mlp1<<<g1, 256>>>(w1, b1);
    dim3 g2(H_ / T2C, MAXW);       // (24, 64)
    k_mlp2<<<g2, 256>>>(w2, b2, out);
}